// round 4
// baseline (speedup 1.0000x reference)
#include <cuda_runtime.h>
#include <math.h>
#include <stdint.h>

#define BB 64
#define TT 2048
#define DENC 512
#define DRNN 1024
#define DATT 128
#define NFQ 32
#define KW 31
#define PADW 15
#define NSPLIT 32

typedef unsigned long long ull;

__device__ float g_pq[BB * DATT];
__device__ float g_part[BB * NSPLIT * DENC];
__device__ __align__(16) float g_dfa[NFQ * DATT];  // densew transposed to [f][a]

__device__ __forceinline__ float tanh_fast(float x) {
    float y;
    asm("tanh.approx.f32 %0, %1;" : "=f"(y) : "f"(x));
    return y;
}
__device__ __forceinline__ ull pack2(float lo, float hi) {
    ull r;
    asm("mov.b64 %0, {%1, %2};" : "=l"(r) : "f"(lo), "f"(hi));
    return r;
}
__device__ __forceinline__ void unpack2(ull v, float& lo, float& hi) {
    asm("mov.b64 {%0, %1}, %2;" : "=f"(lo), "=f"(hi) : "l"(v));
}
__device__ __forceinline__ ull fma2(ull a, ull b, ull c) {
    ull d;
    asm("fma.rn.f32x2 %0, %1, %2, %3;" : "=l"(d) : "l"(a), "l"(b), "l"(c));
    return d;
}
__device__ __forceinline__ ull add2(ull a, ull b) {
    ull d;
    asm("add.rn.f32x2 %0, %1, %2;" : "=l"(d) : "l"(a), "l"(b));
    return d;
}

// ---------------------------------------------------------------------------
// Prep: transpose densew [a][f] -> g_dfa [f][a]  (tiny, 4096 elems)
// ---------------------------------------------------------------------------
__global__ __launch_bounds__(256) void prep_dense(const float* __restrict__ densew) {
    const int i = blockIdx.x * 256 + threadIdx.x;  // i = f*128 + a
    const int f = i >> 7, a = i & 127;
    g_dfa[i] = densew[a * NFQ + f];
}

// ---------------------------------------------------------------------------
// Kernel A: pq[b,a] = sum_d ahs[b,d] * qw[a,d]
// ---------------------------------------------------------------------------
__global__ __launch_bounds__(256) void pq_kernel(const float* __restrict__ ahs,
                                                 const float* __restrict__ qw) {
    const int b = blockIdx.x;
    __shared__ __align__(16) float ahs_s[DRNN];
    for (int i = threadIdx.x; i < DRNN / 4; i += 256)
        reinterpret_cast<float4*>(ahs_s)[i] =
            reinterpret_cast<const float4*>(ahs + (size_t)b * DRNN)[i];
    __syncthreads();
    const int w = threadIdx.x >> 5, lane = threadIdx.x & 31;
    for (int a = w; a < DATT; a += 8) {
        const float4* qr = reinterpret_cast<const float4*>(qw + (size_t)a * DRNN);
        float acc = 0.f;
        #pragma unroll
        for (int d4 = lane; d4 < DRNN / 4; d4 += 32) {
            const float4 q = qr[d4];
            const float4 h = reinterpret_cast<const float4*>(ahs_s)[d4];
            acc += q.x * h.x + q.y * h.y + q.z * h.z + q.w * h.w;
        }
        #pragma unroll
        for (int off = 16; off; off >>= 1) acc += __shfl_xor_sync(0xffffffffu, acc, off);
        if (lane == 0) g_pq[b * DATT + a] = acc;
    }
}

// ---------------------------------------------------------------------------
// Kernel B: fused location-conv + dense + tanh + value-dot -> alignment logits
// Block = 128 threads, 32 t's. Warp w covers a-range [32w,32w+32).
// Dense + energies use packed f32x2 (FFMA2).
// ---------------------------------------------------------------------------
__global__ __launch_bounds__(128) void align_kernel(
    const float* __restrict__ pm,      // [B,T,128]
    const float* __restrict__ awc,     // [B,2,T]
    const float* __restrict__ convw,   // [32,2,31]
    const float* __restrict__ vw,      // [128]
    float* __restrict__ align_out)     // [B,T] logits
{
    const int b = blockIdx.y;
    const int t0 = blockIdx.x * 32;
    const int tid = threadIdx.x;
    const int w = tid >> 5, lane = tid & 31;
    const int tg = lane >> 2, ag = lane & 3;

    __shared__ __align__(16) float pq_s[DATT];
    __shared__ __align__(16) float val_s[DATT];
    __shared__ __align__(16) float dense_s[NFQ * DATT];   // [f][a]
    __shared__ float convw_s[NFQ * 2 * KW];               // [f][c][k]
    __shared__ float awc_s[2][62];
    __shared__ __align__(16) float loc_s[NFQ * 32];       // [f][tt]
    __shared__ float part_s[4][32];

    // ---- stage shared (all coalesced now) ----
    if (tid < DATT) { pq_s[tid] = g_pq[b * DATT + tid]; val_s[tid] = vw[tid]; }
    #pragma unroll
    for (int i = tid; i < NFQ * DATT / 4; i += 128)
        reinterpret_cast<float4*>(dense_s)[i] = reinterpret_cast<const float4*>(g_dfa)[i];
    for (int i = tid; i < NFQ * 2 * KW; i += 128) convw_s[i] = convw[i];
    if (tid < 124) {
        int c = tid / 62, p = tid - c * 62;
        int pos = t0 - PADW + p;
        awc_s[c][p] = (pos >= 0 && pos < TT) ? awc[((size_t)b * 2 + c) * TT + pos] : 0.f;
    }
    __syncthreads();

    // ---- conv: thread computes f = tid>>2, tt range [(tid&3)*8, +8) ----
    {
        const int f = tid >> 2;
        const int ttb = (tid & 3) * 8;
        const float* cw = convw_s + f * 62;
        float acc[8], w0r[8], w1r[8];
        #pragma unroll
        for (int j = 0; j < 8; j++) {
            acc[j] = 0.f;
            w0r[j] = awc_s[0][ttb + j];
            w1r[j] = awc_s[1][ttb + j];
        }
        #pragma unroll
        for (int k = 0; k < KW; k++) {
            const float wk0 = cw[k], wk1 = cw[KW + k];
            #pragma unroll
            for (int j = 0; j < 8; j++) {
                const int r = (k + j) & 7;
                acc[j] += w0r[r] * wk0 + w1r[r] * wk1;
            }
            if (k < KW - 1) {
                w0r[k & 7] = awc_s[0][ttb + k + 8];
                w1r[k & 7] = awc_s[1][ttb + k + 8];
            }
        }
        #pragma unroll
        for (int j = 0; j < 8; j++) loc_s[f * 32 + ttb + j] = acc[j];
    }
    __syncthreads();

    // ---- dense (packed): acc2p[i][jj] covers t = t0+tg*4+i, a = abase+2jj..+2jj+1
    const int abase = w * 32 + ag * 8;
    ull acc2p[4][4];
    #pragma unroll
    for (int i = 0; i < 4; i++)
        #pragma unroll
        for (int jj = 0; jj < 4; jj++) acc2p[i][jj] = 0ull;

    #pragma unroll 4
    for (int f = 0; f < NFQ; f++) {
        const float4 lv = *reinterpret_cast<const float4*>(&loc_s[f * 32 + tg * 4]);
        const ulonglong2* dp =
            reinterpret_cast<const ulonglong2*>(&dense_s[f * DATT + abase]);
        const ulonglong2 q0 = dp[0], q1 = dp[1];
        const ull dvp[4] = {q0.x, q0.y, q1.x, q1.y};
        ull lvp[4];
        lvp[0] = pack2(lv.x, lv.x);
        lvp[1] = pack2(lv.y, lv.y);
        lvp[2] = pack2(lv.z, lv.z);
        lvp[3] = pack2(lv.w, lv.w);
        #pragma unroll
        for (int i = 0; i < 4; i++)
            #pragma unroll
            for (int jj = 0; jj < 4; jj++)
                acc2p[i][jj] = fma2(lvp[i], dvp[jj], acc2p[i][jj]);
    }

    // pq pairs (direct 64-bit loads) and value weights (scalar)
    const ulonglong2* pqp = reinterpret_cast<const ulonglong2*>(&pq_s[abase]);
    const ulonglong2 pqa = pqp[0], pqb = pqp[1];
    const ull pq2[4] = {pqa.x, pqa.y, pqb.x, pqb.y};
    float vr[8];
    #pragma unroll
    for (int j = 0; j < 8; j++) vr[j] = val_s[abase + j];

    // ---- energies + partial value-dot ----
    #pragma unroll
    for (int i = 0; i < 4; i++) {
        const int t = t0 + tg * 4 + i;
        const ulonglong2* pmp = reinterpret_cast<const ulonglong2*>(
            pm + ((size_t)b * TT + t) * DATT + abase);
        const ulonglong2 m0 = pmp[0], m1 = pmp[1];
        const ull pv[4] = {m0.x, m0.y, m1.x, m1.y};
        float s = 0.f;
        #pragma unroll
        for (int jj = 0; jj < 4; jj++) {
            const ull e2 = add2(add2(pq2[jj], pv[jj]), acc2p[i][jj]);
            float elo, ehi;
            unpack2(e2, elo, ehi);
            s += tanh_fast(elo) * vr[2 * jj] + tanh_fast(ehi) * vr[2 * jj + 1];
        }
        s += __shfl_xor_sync(0xffffffffu, s, 1);
        s += __shfl_xor_sync(0xffffffffu, s, 2);
        if (ag == 0) part_s[w][tg * 4 + i] = s;
    }
    __syncthreads();
    if (tid < 32) {
        const float s = part_s[0][tid] + part_s[1][tid] + part_s[2][tid] + part_s[3][tid];
        align_out[(size_t)b * TT + t0 + tid] = s;
    }
}

// ---------------------------------------------------------------------------
// Kernel C: per-row softmax over T with mask (in place on logits)
// ---------------------------------------------------------------------------
__global__ __launch_bounds__(512) void softmax_kernel(float* __restrict__ row_base,
                                                      const unsigned char* __restrict__ mask) {
    const int b = blockIdx.x;
    float* row = row_base + (size_t)b * TT;
    const unsigned char* mrow = mask + (size_t)b * TT;
    __shared__ float sh[16];
    const int lane = threadIdx.x & 31, wid = threadIdx.x >> 5;

    float m = -INFINITY;
    for (int t = threadIdx.x; t < TT; t += 512) {
        float v = mrow[t] ? -INFINITY : row[t];
        m = fmaxf(m, v);
    }
    #pragma unroll
    for (int o = 16; o; o >>= 1) m = fmaxf(m, __shfl_xor_sync(0xffffffffu, m, o));
    if (lane == 0) sh[wid] = m;
    __syncthreads();
    m = (lane < 16) ? sh[lane] : -INFINITY;
    #pragma unroll
    for (int o = 8; o; o >>= 1) m = fmaxf(m, __shfl_xor_sync(0xffffffffu, m, o));
    if (threadIdx.x == 0) sh[0] = m;
    __syncthreads();
    m = sh[0];
    __syncthreads();

    float s = 0.f;
    for (int t = threadIdx.x; t < TT; t += 512) {
        float v = mrow[t] ? -INFINITY : row[t];
        s += __expf(v - m);
    }
    #pragma unroll
    for (int o = 16; o; o >>= 1) s += __shfl_xor_sync(0xffffffffu, s, o);
    if (lane == 0) sh[wid] = s;
    __syncthreads();
    s = (lane < 16) ? sh[lane] : 0.f;
    #pragma unroll
    for (int o = 8; o; o >>= 1) s += __shfl_xor_sync(0xffffffffu, s, o);
    if (threadIdx.x == 0) sh[0] = s;
    __syncthreads();
    const float inv = 1.f / sh[0];

    for (int t = threadIdx.x; t < TT; t += 512) {
        float v = mrow[t] ? -INFINITY : row[t];
        row[t] = __expf(v - m) * inv;
    }
}

// ---------------------------------------------------------------------------
// Kernel D: context partial sums (memory-bound: streams `memory`)
// ---------------------------------------------------------------------------
__global__ __launch_bounds__(128) void ctx_partial(const float* __restrict__ mem,
                                                   const float* __restrict__ wts) {
    const int b = blockIdx.y, s = blockIdx.x;
    constexpr int TC = TT / NSPLIT;  // 64
    const int t0 = s * TC;
    __shared__ float w_s[TC];
    if (threadIdx.x < TC) w_s[threadIdx.x] = wts[(size_t)b * TT + t0 + threadIdx.x];
    __syncthreads();
    const float4* mrow = reinterpret_cast<const float4*>(
        mem + ((size_t)b * TT + t0) * DENC) + threadIdx.x;
    float4 acc = make_float4(0.f, 0.f, 0.f, 0.f);
    #pragma unroll 8
    for (int i = 0; i < TC; i++) {
        const float wv = w_s[i];
        const float4 m = mrow[(size_t)i * (DENC / 4)];
        acc.x += wv * m.x;
        acc.y += wv * m.y;
        acc.z += wv * m.z;
        acc.w += wv * m.w;
    }
    reinterpret_cast<float4*>(g_part + ((size_t)b * NSPLIT + s) * DENC)[threadIdx.x] = acc;
}

// ---------------------------------------------------------------------------
// Kernel E: reduce partials -> context
// ---------------------------------------------------------------------------
__global__ __launch_bounds__(128) void ctx_reduce(float* __restrict__ ctx) {
    const int b = blockIdx.x;
    float4 acc = make_float4(0.f, 0.f, 0.f, 0.f);
    #pragma unroll
    for (int s = 0; s < NSPLIT; s++) {
        const float4 p = reinterpret_cast<const float4*>(
            g_part + ((size_t)b * NSPLIT + s) * DENC)[threadIdx.x];
        acc.x += p.x; acc.y += p.y; acc.z += p.z; acc.w += p.w;
    }
    reinterpret_cast<float4*>(ctx + (size_t)b * DENC)[threadIdx.x] = acc;
}

// ---------------------------------------------------------------------------
// Entry
// ---------------------------------------------------------------------------
extern "C" void kernel_launch(void* const* d_in, const int* in_sizes, int n_in,
                              void* d_out, int out_size) {
    const float* ahs    = (const float*)d_in[0];
    const float* mem    = (const float*)d_in[1];
    const float* pm     = (const float*)d_in[2];
    const float* awc    = (const float*)d_in[3];
    const unsigned char* mask = (const unsigned char*)d_in[4];
    const float* qw     = (const float*)d_in[5];
    const float* vw     = (const float*)d_in[6];
    const float* convw  = (const float*)d_in[7];
    const float* densew = (const float*)d_in[8];

    float* out = (float*)d_out;
    float* ctx = out;               // [B, D_ENC]
    float* wts = out + BB * DENC;   // [B, T]

    prep_dense<<<NFQ * DATT / 256, 256>>>(densew);
    pq_kernel<<<BB, 256>>>(ahs, qw);
    align_kernel<<<dim3(TT / 32, BB), 128>>>(pm, awc, convw, vw, wts);
    softmax_kernel<<<BB, 512>>>(wts, mask);
    ctx_partial<<<dim3(NSPLIT, BB), 128>>>(mem, wts);
    ctx_reduce<<<BB, 128>>>(ctx);
}

// round 5
// speedup vs baseline: 1.1700x; 1.1700x over previous
#include <cuda_runtime.h>
#include <math.h>
#include <stdint.h>

#define BB 64
#define TT 2048
#define DENC 512
#define DRNN 1024
#define DATT 128
#define NFQ 32
#define KW 31
#define PADW 15
#define NSPLIT 32

typedef unsigned long long ull;

__device__ float g_pq[BB * DATT];
__device__ float g_part[BB * NSPLIT * DENC];
__device__ __align__(16) float g_dfa[NFQ * DATT];  // densew transposed to [f][a]

__device__ __forceinline__ float tanh_fast(float x) {
    float y;
    asm("tanh.approx.f32 %0, %1;" : "=f"(y) : "f"(x));
    return y;
}
__device__ __forceinline__ ull pack2(float lo, float hi) {
    ull r;
    asm("mov.b64 %0, {%1, %2};" : "=l"(r) : "f"(lo), "f"(hi));
    return r;
}
__device__ __forceinline__ void unpack2(ull v, float& lo, float& hi) {
    asm("mov.b64 {%0, %1}, %2;" : "=f"(lo), "=f"(hi) : "l"(v));
}
__device__ __forceinline__ ull fma2(ull a, ull b, ull c) {
    ull d;
    asm("fma.rn.f32x2 %0, %1, %2, %3;" : "=l"(d) : "l"(a), "l"(b), "l"(c));
    return d;
}
__device__ __forceinline__ ull add2(ull a, ull b) {
    ull d;
    asm("add.rn.f32x2 %0, %1, %2;" : "=l"(d) : "l"(a), "l"(b));
    return d;
}

// ---------------------------------------------------------------------------
// Prep: transpose densew [a][f] -> g_dfa [f][a]  (tiny, 4096 elems)
// ---------------------------------------------------------------------------
__global__ __launch_bounds__(256) void prep_dense(const float* __restrict__ densew) {
    const int i = blockIdx.x * 256 + threadIdx.x;  // i = f*128 + a
    const int f = i >> 7, a = i & 127;
    g_dfa[i] = densew[a * NFQ + f];
}

// ---------------------------------------------------------------------------
// Kernel A: pq[b,a] = sum_d ahs[b,d] * qw[a,d]
// ---------------------------------------------------------------------------
__global__ __launch_bounds__(256) void pq_kernel(const float* __restrict__ ahs,
                                                 const float* __restrict__ qw) {
    const int b = blockIdx.x;
    __shared__ __align__(16) float ahs_s[DRNN];
    for (int i = threadIdx.x; i < DRNN / 4; i += 256)
        reinterpret_cast<float4*>(ahs_s)[i] =
            reinterpret_cast<const float4*>(ahs + (size_t)b * DRNN)[i];
    __syncthreads();
    const int w = threadIdx.x >> 5, lane = threadIdx.x & 31;
    for (int a = w; a < DATT; a += 8) {
        const float4* qr = reinterpret_cast<const float4*>(qw + (size_t)a * DRNN);
        float acc = 0.f;
        #pragma unroll
        for (int d4 = lane; d4 < DRNN / 4; d4 += 32) {
            const float4 q = qr[d4];
            const float4 h = reinterpret_cast<const float4*>(ahs_s)[d4];
            acc += q.x * h.x + q.y * h.y + q.z * h.z + q.w * h.w;
        }
        #pragma unroll
        for (int off = 16; off; off >>= 1) acc += __shfl_xor_sync(0xffffffffu, acc, off);
        if (lane == 0) g_pq[b * DATT + a] = acc;
    }
}

// ---------------------------------------------------------------------------
// Kernel B: fused location-conv + dense + tanh + value-dot -> alignment logits
// Block = 128 threads, 32 t's. Warp w covers a-range [32w,32w+32).
// Dense + energies use packed f32x2 (FFMA2).
// ---------------------------------------------------------------------------
__global__ __launch_bounds__(128) void align_kernel(
    const float* __restrict__ pm,      // [B,T,128]
    const float* __restrict__ awc,     // [B,2,T]
    const float* __restrict__ convw,   // [32,2,31]
    const float* __restrict__ vw,      // [128]
    float* __restrict__ align_out)     // [B,T] logits
{
    const int b = blockIdx.y;
    const int t0 = blockIdx.x * 32;
    const int tid = threadIdx.x;
    const int w = tid >> 5, lane = tid & 31;
    const int tg = lane >> 2, ag = lane & 3;

    __shared__ __align__(16) float pq_s[DATT];
    __shared__ __align__(16) float val_s[DATT];
    __shared__ __align__(16) float dense_s[NFQ * DATT];   // [f][a]
    __shared__ float convw_s[NFQ * 2 * KW];               // [f][c][k]
    __shared__ float awc_s[2][62];
    __shared__ __align__(16) float loc_s[NFQ * 32];       // [f][tt]
    __shared__ float part_s[4][32];

    // ---- stage shared (all coalesced now) ----
    if (tid < DATT) { pq_s[tid] = g_pq[b * DATT + tid]; val_s[tid] = vw[tid]; }
    #pragma unroll
    for (int i = tid; i < NFQ * DATT / 4; i += 128)
        reinterpret_cast<float4*>(dense_s)[i] = reinterpret_cast<const float4*>(g_dfa)[i];
    for (int i = tid; i < NFQ * 2 * KW; i += 128) convw_s[i] = convw[i];
    if (tid < 124) {
        int c = tid / 62, p = tid - c * 62;
        int pos = t0 - PADW + p;
        awc_s[c][p] = (pos >= 0 && pos < TT) ? awc[((size_t)b * 2 + c) * TT + pos] : 0.f;
    }
    __syncthreads();

    // ---- conv: thread computes f = tid>>2, tt range [(tid&3)*8, +8) ----
    {
        const int f = tid >> 2;
        const int ttb = (tid & 3) * 8;
        const float* cw = convw_s + f * 62;
        float acc[8], w0r[8], w1r[8];
        #pragma unroll
        for (int j = 0; j < 8; j++) {
            acc[j] = 0.f;
            w0r[j] = awc_s[0][ttb + j];
            w1r[j] = awc_s[1][ttb + j];
        }
        #pragma unroll
        for (int k = 0; k < KW; k++) {
            const float wk0 = cw[k], wk1 = cw[KW + k];
            #pragma unroll
            for (int j = 0; j < 8; j++) {
                const int r = (k + j) & 7;
                acc[j] += w0r[r] * wk0 + w1r[r] * wk1;
            }
            if (k < KW - 1) {
                w0r[k & 7] = awc_s[0][ttb + k + 8];
                w1r[k & 7] = awc_s[1][ttb + k + 8];
            }
        }
        #pragma unroll
        for (int j = 0; j < 8; j++) loc_s[f * 32 + ttb + j] = acc[j];
    }
    __syncthreads();

    // ---- dense (packed): acc2p[i][jj] covers t = t0+tg*4+i, a = abase+2jj..+2jj+1
    const int abase = w * 32 + ag * 8;
    ull acc2p[4][4];
    #pragma unroll
    for (int i = 0; i < 4; i++)
        #pragma unroll
        for (int jj = 0; jj < 4; jj++) acc2p[i][jj] = 0ull;

    #pragma unroll 4
    for (int f = 0; f < NFQ; f++) {
        const float4 lv = *reinterpret_cast<const float4*>(&loc_s[f * 32 + tg * 4]);
        const ulonglong2* dp =
            reinterpret_cast<const ulonglong2*>(&dense_s[f * DATT + abase]);
        const ulonglong2 q0 = dp[0], q1 = dp[1];
        const ull dvp[4] = {q0.x, q0.y, q1.x, q1.y};
        ull lvp[4];
        lvp[0] = pack2(lv.x, lv.x);
        lvp[1] = pack2(lv.y, lv.y);
        lvp[2] = pack2(lv.z, lv.z);
        lvp[3] = pack2(lv.w, lv.w);
        #pragma unroll
        for (int i = 0; i < 4; i++)
            #pragma unroll
            for (int jj = 0; jj < 4; jj++)
                acc2p[i][jj] = fma2(lvp[i], dvp[jj], acc2p[i][jj]);
    }

    // pq pairs (direct 64-bit loads) and value weights (scalar)
    const ulonglong2* pqp = reinterpret_cast<const ulonglong2*>(&pq_s[abase]);
    const ulonglong2 pqa = pqp[0], pqb = pqp[1];
    const ull pq2[4] = {pqa.x, pqa.y, pqb.x, pqb.y};
    float vr[8];
    #pragma unroll
    for (int j = 0; j < 8; j++) vr[j] = val_s[abase + j];

    // ---- energies + partial value-dot ----
    #pragma unroll
    for (int i = 0; i < 4; i++) {
        const int t = t0 + tg * 4 + i;
        const ulonglong2* pmp = reinterpret_cast<const ulonglong2*>(
            pm + ((size_t)b * TT + t) * DATT + abase);
        const ulonglong2 m0 = pmp[0], m1 = pmp[1];
        const ull pv[4] = {m0.x, m0.y, m1.x, m1.y};
        float s = 0.f;
        #pragma unroll
        for (int jj = 0; jj < 4; jj++) {
            const ull e2 = add2(add2(pq2[jj], pv[jj]), acc2p[i][jj]);
            float elo, ehi;
            unpack2(e2, elo, ehi);
            s += tanh_fast(elo) * vr[2 * jj] + tanh_fast(ehi) * vr[2 * jj + 1];
        }
        s += __shfl_xor_sync(0xffffffffu, s, 1);
        s += __shfl_xor_sync(0xffffffffu, s, 2);
        if (ag == 0) part_s[w][tg * 4 + i] = s;
    }
    __syncthreads();
    if (tid < 32) {
        const float s = part_s[0][tid] + part_s[1][tid] + part_s[2][tid] + part_s[3][tid];
        align_out[(size_t)b * TT + t0 + tid] = s;
    }
}

// ---------------------------------------------------------------------------
// Kernel C: per-row softmax over T with mask (in place on logits)
// ---------------------------------------------------------------------------
__global__ __launch_bounds__(512) void softmax_kernel(float* __restrict__ row_base,
                                                      const unsigned char* __restrict__ mask) {
    const int b = blockIdx.x;
    float* row = row_base + (size_t)b * TT;
    const unsigned char* mrow = mask + (size_t)b * TT;
    __shared__ float sh[16];
    const int lane = threadIdx.x & 31, wid = threadIdx.x >> 5;

    float m = -INFINITY;
    for (int t = threadIdx.x; t < TT; t += 512) {
        float v = mrow[t] ? -INFINITY : row[t];
        m = fmaxf(m, v);
    }
    #pragma unroll
    for (int o = 16; o; o >>= 1) m = fmaxf(m, __shfl_xor_sync(0xffffffffu, m, o));
    if (lane == 0) sh[wid] = m;
    __syncthreads();
    m = (lane < 16) ? sh[lane] : -INFINITY;
    #pragma unroll
    for (int o = 8; o; o >>= 1) m = fmaxf(m, __shfl_xor_sync(0xffffffffu, m, o));
    if (threadIdx.x == 0) sh[0] = m;
    __syncthreads();
    m = sh[0];
    __syncthreads();

    float s = 0.f;
    for (int t = threadIdx.x; t < TT; t += 512) {
        float v = mrow[t] ? -INFINITY : row[t];
        s += __expf(v - m);
    }
    #pragma unroll
    for (int o = 16; o; o >>= 1) s += __shfl_xor_sync(0xffffffffu, s, o);
    if (lane == 0) sh[wid] = s;
    __syncthreads();
    s = (lane < 16) ? sh[lane] : 0.f;
    #pragma unroll
    for (int o = 8; o; o >>= 1) s += __shfl_xor_sync(0xffffffffu, s, o);
    if (threadIdx.x == 0) sh[0] = s;
    __syncthreads();
    const float inv = 1.f / sh[0];

    for (int t = threadIdx.x; t < TT; t += 512) {
        float v = mrow[t] ? -INFINITY : row[t];
        row[t] = __expf(v - m) * inv;
    }
}

// ---------------------------------------------------------------------------
// Kernel D: context partial sums (memory-bound: streams `memory`)
// ---------------------------------------------------------------------------
__global__ __launch_bounds__(128) void ctx_partial(const float* __restrict__ mem,
                                                   const float* __restrict__ wts) {
    const int b = blockIdx.y, s = blockIdx.x;
    constexpr int TC = TT / NSPLIT;  // 64
    const int t0 = s * TC;
    __shared__ float w_s[TC];
    if (threadIdx.x < TC) w_s[threadIdx.x] = wts[(size_t)b * TT + t0 + threadIdx.x];
    __syncthreads();
    const float4* mrow = reinterpret_cast<const float4*>(
        mem + ((size_t)b * TT + t0) * DENC) + threadIdx.x;
    float4 acc = make_float4(0.f, 0.f, 0.f, 0.f);
    #pragma unroll 8
    for (int i = 0; i < TC; i++) {
        const float wv = w_s[i];
        const float4 m = mrow[(size_t)i * (DENC / 4)];
        acc.x += wv * m.x;
        acc.y += wv * m.y;
        acc.z += wv * m.z;
        acc.w += wv * m.w;
    }
    reinterpret_cast<float4*>(g_part + ((size_t)b * NSPLIT + s) * DENC)[threadIdx.x] = acc;
}

// ---------------------------------------------------------------------------
// Kernel E: reduce partials -> context
// ---------------------------------------------------------------------------
__global__ __launch_bounds__(128) void ctx_reduce(float* __restrict__ ctx) {
    const int b = blockIdx.x;
    float4 acc = make_float4(0.f, 0.f, 0.f, 0.f);
    #pragma unroll
    for (int s = 0; s < NSPLIT; s++) {
        const float4 p = reinterpret_cast<const float4*>(
            g_part + ((size_t)b * NSPLIT + s) * DENC)[threadIdx.x];
        acc.x += p.x; acc.y += p.y; acc.z += p.z; acc.w += p.w;
    }
    reinterpret_cast<float4*>(ctx + (size_t)b * DENC)[threadIdx.x] = acc;
}

// ---------------------------------------------------------------------------
// Entry
// ---------------------------------------------------------------------------
extern "C" void kernel_launch(void* const* d_in, const int* in_sizes, int n_in,
                              void* d_out, int out_size) {
    const float* ahs    = (const float*)d_in[0];
    const float* mem    = (const float*)d_in[1];
    const float* pm     = (const float*)d_in[2];
    const float* awc    = (const float*)d_in[3];
    const unsigned char* mask = (const unsigned char*)d_in[4];
    const float* qw     = (const float*)d_in[5];
    const float* vw     = (const float*)d_in[6];
    const float* convw  = (const float*)d_in[7];
    const float* densew = (const float*)d_in[8];

    float* out = (float*)d_out;
    float* ctx = out;               // [B, D_ENC]
    float* wts = out + BB * DENC;   // [B, T]

    prep_dense<<<NFQ * DATT / 256, 256>>>(densew);
    pq_kernel<<<BB, 256>>>(ahs, qw);
    align_kernel<<<dim3(TT / 32, BB), 128>>>(pm, awc, convw, vw, wts);
    softmax_kernel<<<BB, 512>>>(wts, mask);
    ctx_partial<<<dim3(NSPLIT, BB), 128>>>(mem, wts);
    ctx_reduce<<<BB, 128>>>(ctx);
}

// round 6
// speedup vs baseline: 1.2906x; 1.1031x over previous
#include <cuda_runtime.h>
#include <math.h>
#include <stdint.h>

#define BB 64
#define TT 2048
#define DENC 512
#define DRNN 1024
#define DATT 128
#define NFQ 32
#define KW 31
#define PADW 15
#define NSPLIT 32
#define SMX 8            // softmax splits per row

typedef unsigned long long ull;

__device__ float g_pq[BB * DATT];
__device__ float g_part[BB * NSPLIT * DENC];
__device__ __align__(16) float g_dfa[NFQ * DATT];  // densew transposed to [f][a]
__device__ float g_smax[BB * SMX];
__device__ float g_ssum[BB * SMX];

__device__ __forceinline__ float tanh_fast(float x) {
    float y;
    asm("tanh.approx.f32 %0, %1;" : "=f"(y) : "f"(x));
    return y;
}
__device__ __forceinline__ ull pack2(float lo, float hi) {
    ull r;
    asm("mov.b64 %0, {%1, %2};" : "=l"(r) : "f"(lo), "f"(hi));
    return r;
}
__device__ __forceinline__ void unpack2(ull v, float& lo, float& hi) {
    asm("mov.b64 {%0, %1}, %2;" : "=f"(lo), "=f"(hi) : "l"(v));
}
__device__ __forceinline__ ull fma2(ull a, ull b, ull c) {
    ull d;
    asm("fma.rn.f32x2 %0, %1, %2, %3;" : "=l"(d) : "l"(a), "l"(b), "l"(c));
    return d;
}
__device__ __forceinline__ ull add2(ull a, ull b) {
    ull d;
    asm("add.rn.f32x2 %0, %1, %2;" : "=l"(d) : "l"(a), "l"(b));
    return d;
}

// ---------------------------------------------------------------------------
// Prep: transpose densew [a][f] -> g_dfa [f][a]
// ---------------------------------------------------------------------------
__global__ __launch_bounds__(256) void prep_dense(const float* __restrict__ densew) {
    const int i = blockIdx.x * 256 + threadIdx.x;  // i = f*128 + a
    const int f = i >> 7, a = i & 127;
    g_dfa[i] = densew[a * NFQ + f];
}

// ---------------------------------------------------------------------------
// Kernel A: pq[b,a] = sum_d ahs[b,d] * qw[a,d]   grid (B, 4), each block 32 a's
// ---------------------------------------------------------------------------
__global__ __launch_bounds__(128) void pq_kernel(const float* __restrict__ ahs,
                                                 const float* __restrict__ qw) {
    const int b = blockIdx.x;
    const int abase = blockIdx.y * 32;
    __shared__ __align__(16) float ahs_s[DRNN];
    for (int i = threadIdx.x; i < DRNN / 4; i += 128)
        reinterpret_cast<float4*>(ahs_s)[i] =
            reinterpret_cast<const float4*>(ahs + (size_t)b * DRNN)[i];
    __syncthreads();
    const int w = threadIdx.x >> 5, lane = threadIdx.x & 31;
    #pragma unroll
    for (int aa = 0; aa < 8; aa++) {
        const int a = abase + w * 8 + aa;
        const float4* qr = reinterpret_cast<const float4*>(qw + (size_t)a * DRNN);
        float acc = 0.f;
        #pragma unroll
        for (int d4 = lane; d4 < DRNN / 4; d4 += 32) {
            const float4 q = qr[d4];
            const float4 h = reinterpret_cast<const float4*>(ahs_s)[d4];
            acc += q.x * h.x + q.y * h.y + q.z * h.z + q.w * h.w;
        }
        #pragma unroll
        for (int off = 16; off; off >>= 1) acc += __shfl_xor_sync(0xffffffffu, acc, off);
        if (lane == 0) g_pq[b * DATT + a] = acc;
    }
}

// ---------------------------------------------------------------------------
// Kernel B: fused location-conv + dense + tanh + value-dot -> alignment logits
// Block = 256 threads, 64 t's. Warp w: t-half = w>>2, a-range [(w&3)*32, +32).
// ---------------------------------------------------------------------------
__global__ __launch_bounds__(256) void align_kernel(
    const float* __restrict__ pm,      // [B,T,128]
    const float* __restrict__ awc,     // [B,2,T]
    const float* __restrict__ convw,   // [32,2,31]
    const float* __restrict__ vw,      // [128]
    float* __restrict__ align_out)     // [B,T] logits
{
    const int b = blockIdx.y;
    const int t0 = blockIdx.x * 64;
    const int tid = threadIdx.x;
    const int w = tid >> 5, lane = tid & 31;
    const int thalf = w >> 2, aw = w & 3;
    const int tg = lane >> 2, ag = lane & 3;

    __shared__ __align__(16) float pq_s[DATT];
    __shared__ __align__(16) float val_s[DATT];
    __shared__ __align__(16) float dense_s[NFQ * DATT];   // [f][a]
    __shared__ float convw_s[NFQ * 2 * KW];               // [f][c][k]
    __shared__ float awc_s[2][94];                        // 64 + 2*15
    __shared__ __align__(16) float loc_s[NFQ * 64];       // [f][tt]
    __shared__ float part_s[2][4][32];

    // ---- stage shared (coalesced) ----
    if (tid < DATT) { pq_s[tid] = g_pq[b * DATT + tid]; val_s[tid] = vw[tid]; }
    #pragma unroll
    for (int i = tid; i < NFQ * DATT / 4; i += 256)
        reinterpret_cast<float4*>(dense_s)[i] = reinterpret_cast<const float4*>(g_dfa)[i];
    for (int i = tid; i < NFQ * 2 * KW; i += 256) convw_s[i] = convw[i];
    if (tid < 188) {
        int c = tid / 94, p = tid - c * 94;
        int pos = t0 - PADW + p;
        awc_s[c][p] = (pos >= 0 && pos < TT) ? awc[((size_t)b * 2 + c) * TT + pos] : 0.f;
    }
    __syncthreads();

    // ---- conv: thread computes f = tid>>3, tt range [(tid&7)*8, +8) ----
    {
        const int f = tid >> 3;
        const int ttb = (tid & 7) * 8;
        const float* cw = convw_s + f * 62;
        float acc[8], w0r[8], w1r[8];
        #pragma unroll
        for (int j = 0; j < 8; j++) {
            acc[j] = 0.f;
            w0r[j] = awc_s[0][ttb + j];
            w1r[j] = awc_s[1][ttb + j];
        }
        #pragma unroll
        for (int k = 0; k < KW; k++) {
            const float wk0 = cw[k], wk1 = cw[KW + k];
            #pragma unroll
            for (int j = 0; j < 8; j++) {
                const int r = (k + j) & 7;
                acc[j] += w0r[r] * wk0 + w1r[r] * wk1;
            }
            if (k < KW - 1) {
                w0r[k & 7] = awc_s[0][ttb + k + 8];
                w1r[k & 7] = awc_s[1][ttb + k + 8];
            }
        }
        #pragma unroll
        for (int j = 0; j < 8; j++) loc_s[f * 64 + ttb + j] = acc[j];
    }
    __syncthreads();

    // ---- dense (packed f32x2): lane tile = 4t x 8a ----
    const int abase = aw * 32 + ag * 8;
    const int tloc = thalf * 32 + tg * 4;   // local t of first row in tile
    ull acc2p[4][4];
    #pragma unroll
    for (int i = 0; i < 4; i++)
        #pragma unroll
        for (int jj = 0; jj < 4; jj++) acc2p[i][jj] = 0ull;

    #pragma unroll 4
    for (int f = 0; f < NFQ; f++) {
        const float4 lv = *reinterpret_cast<const float4*>(&loc_s[f * 64 + tloc]);
        const ulonglong2* dp =
            reinterpret_cast<const ulonglong2*>(&dense_s[f * DATT + abase]);
        const ulonglong2 q0 = dp[0], q1 = dp[1];
        const ull dvp[4] = {q0.x, q0.y, q1.x, q1.y};
        ull lvp[4];
        lvp[0] = pack2(lv.x, lv.x);
        lvp[1] = pack2(lv.y, lv.y);
        lvp[2] = pack2(lv.z, lv.z);
        lvp[3] = pack2(lv.w, lv.w);
        #pragma unroll
        for (int i = 0; i < 4; i++)
            #pragma unroll
            for (int jj = 0; jj < 4; jj++)
                acc2p[i][jj] = fma2(lvp[i], dvp[jj], acc2p[i][jj]);
    }

    const ulonglong2* pqp = reinterpret_cast<const ulonglong2*>(&pq_s[abase]);
    const ulonglong2 pqa = pqp[0], pqb = pqp[1];
    const ull pq2[4] = {pqa.x, pqa.y, pqb.x, pqb.y};
    float vr[8];
    #pragma unroll
    for (int j = 0; j < 8; j++) vr[j] = val_s[abase + j];

    // ---- energies + partial value-dot ----
    #pragma unroll
    for (int i = 0; i < 4; i++) {
        const int t = t0 + tloc + i;
        const ulonglong2* pmp = reinterpret_cast<const ulonglong2*>(
            pm + ((size_t)b * TT + t) * DATT + abase);
        const ulonglong2 m0 = pmp[0], m1 = pmp[1];
        const ull pv[4] = {m0.x, m0.y, m1.x, m1.y};
        float s = 0.f;
        #pragma unroll
        for (int jj = 0; jj < 4; jj++) {
            const ull e2 = add2(add2(pq2[jj], pv[jj]), acc2p[i][jj]);
            float elo, ehi;
            unpack2(e2, elo, ehi);
            s += tanh_fast(elo) * vr[2 * jj] + tanh_fast(ehi) * vr[2 * jj + 1];
        }
        s += __shfl_xor_sync(0xffffffffu, s, 1);
        s += __shfl_xor_sync(0xffffffffu, s, 2);
        if (ag == 0) part_s[thalf][aw][tg * 4 + i] = s;
    }
    __syncthreads();
    if (tid < 64) {
        const int th = tid >> 5, tt = tid & 31;
        const float s = part_s[th][0][tt] + part_s[th][1][tt] +
                        part_s[th][2][tt] + part_s[th][3][tt];
        align_out[(size_t)b * TT + t0 + th * 32 + tt] = s;
    }
}

// ---------------------------------------------------------------------------
// Kernel C1: partial softmax stats per (b, split of 256 t's)
// ---------------------------------------------------------------------------
__global__ __launch_bounds__(256) void softmax_part(const float* __restrict__ row_base,
                                                    const unsigned char* __restrict__ mask) {
    const int b = blockIdx.y, s = blockIdx.x;
    const int t0 = s * (TT / SMX);
    const float* row = row_base + (size_t)b * TT + t0;
    const unsigned char* mrow = mask + (size_t)b * TT + t0;
    __shared__ float shm[8], shs[8];
    const int lane = threadIdx.x & 31, wid = threadIdx.x >> 5;

    const float x = mrow[threadIdx.x] ? -INFINITY : row[threadIdx.x];
    float m = x;
    #pragma unroll
    for (int o = 16; o; o >>= 1) m = fmaxf(m, __shfl_xor_sync(0xffffffffu, m, o));
    if (lane == 0) shm[wid] = m;
    __syncthreads();
    float bm = shm[0];
    #pragma unroll
    for (int i = 1; i < 8; i++) bm = fmaxf(bm, shm[i]);

    float e = (x == -INFINITY) ? 0.f : __expf(x - bm);
    #pragma unroll
    for (int o = 16; o; o >>= 1) e += __shfl_xor_sync(0xffffffffu, e, o);
    if (lane == 0) shs[wid] = e;
    __syncthreads();
    if (threadIdx.x == 0) {
        float sum = shs[0] + shs[1] + shs[2] + shs[3] + shs[4] + shs[5] + shs[6] + shs[7];
        g_smax[b * SMX + s] = bm;
        g_ssum[b * SMX + s] = sum;
    }
}

// ---------------------------------------------------------------------------
// Kernel C2: combine stats + normalize
// ---------------------------------------------------------------------------
__global__ __launch_bounds__(256) void softmax_norm(float* __restrict__ row_base,
                                                    const unsigned char* __restrict__ mask) {
    const int b = blockIdx.y, s = blockIdx.x;
    const int t = s * (TT / SMX) + threadIdx.x;
    float M = -INFINITY;
    #pragma unroll
    for (int i = 0; i < SMX; i++) M = fmaxf(M, g_smax[b * SMX + i]);
    float S = 0.f;
    #pragma unroll
    for (int i = 0; i < SMX; i++) {
        const float pm = g_smax[b * SMX + i];
        S += (pm == -INFINITY) ? 0.f : g_ssum[b * SMX + i] * __expf(pm - M);
    }
    const float inv = 1.f / S;
    float* row = row_base + (size_t)b * TT;
    const float x = mask[(size_t)b * TT + t] ? -INFINITY : row[t];
    row[t] = (x == -INFINITY) ? 0.f : __expf(x - M) * inv;
}

// ---------------------------------------------------------------------------
// Kernel D: context partial sums (memory-bound: streams `memory`)
// ---------------------------------------------------------------------------
__global__ __launch_bounds__(128) void ctx_partial(const float* __restrict__ mem,
                                                   const float* __restrict__ wts) {
    const int b = blockIdx.y, s = blockIdx.x;
    constexpr int TC = TT / NSPLIT;  // 64
    const int t0 = s * TC;
    __shared__ float w_s[TC];
    if (threadIdx.x < TC) w_s[threadIdx.x] = wts[(size_t)b * TT + t0 + threadIdx.x];
    __syncthreads();
    const float4* mrow = reinterpret_cast<const float4*>(
        mem + ((size_t)b * TT + t0) * DENC) + threadIdx.x;
    float4 acc = make_float4(0.f, 0.f, 0.f, 0.f);
    #pragma unroll 16
    for (int i = 0; i < TC; i++) {
        const float wv = w_s[i];
        const float4 m = mrow[(size_t)i * (DENC / 4)];
        acc.x += wv * m.x;
        acc.y += wv * m.y;
        acc.z += wv * m.z;
        acc.w += wv * m.w;
    }
    reinterpret_cast<float4*>(g_part + ((size_t)b * NSPLIT + s) * DENC)[threadIdx.x] = acc;
}

// ---------------------------------------------------------------------------
// Kernel E: reduce partials -> context
// ---------------------------------------------------------------------------
__global__ __launch_bounds__(128) void ctx_reduce(float* __restrict__ ctx) {
    const int b = blockIdx.x;
    float4 acc = make_float4(0.f, 0.f, 0.f, 0.f);
    #pragma unroll
    for (int s = 0; s < NSPLIT; s++) {
        const float4 p = reinterpret_cast<const float4*>(
            g_part + ((size_t)b * NSPLIT + s) * DENC)[threadIdx.x];
        acc.x += p.x; acc.y += p.y; acc.z += p.z; acc.w += p.w;
    }
    reinterpret_cast<float4*>(ctx + (size_t)b * DENC)[threadIdx.x] = acc;
}

// ---------------------------------------------------------------------------
// Entry
// ---------------------------------------------------------------------------
extern "C" void kernel_launch(void* const* d_in, const int* in_sizes, int n_in,
                              void* d_out, int out_size) {
    const float* ahs    = (const float*)d_in[0];
    const float* mem    = (const float*)d_in[1];
    const float* pm     = (const float*)d_in[2];
    const float* awc    = (const float*)d_in[3];
    const unsigned char* mask = (const unsigned char*)d_in[4];
    const float* qw     = (const float*)d_in[5];
    const float* vw     = (const float*)d_in[6];
    const float* convw  = (const float*)d_in[7];
    const float* densew = (const float*)d_in[8];

    float* out = (float*)d_out;
    float* ctx = out;               // [B, D_ENC]
    float* wts = out + BB * DENC;   // [B, T]

    prep_dense<<<NFQ * DATT / 256, 256>>>(densew);
    pq_kernel<<<dim3(BB, 4), 128>>>(ahs, qw);
    align_kernel<<<dim3(TT / 64, BB), 256>>>(pm, awc, convw, vw, wts);
    softmax_part<<<dim3(SMX, BB), 256>>>(wts, mask);
    softmax_norm<<<dim3(SMX, BB), 256>>>(wts, mask);
    ctx_partial<<<dim3(NSPLIT, BB), 128>>>(mem, wts);
    ctx_reduce<<<BB, 128>>>(ctx);
}